// round 11
// baseline (speedup 1.0000x reference)
#include <cuda_runtime.h>
#include <cuda_bf16.h>
#include <math.h>
#include <float.h>

#define XG 432
#define YG 496
#define CO 64
#define NPT 32
#define PMAX 64000
#define BMAX 4

// Scratch (no allocations allowed anywhere)
__device__ int   g_winner[BMAX * XG * YG];
__device__ float g_pooled[PMAX * CO];

// ---------------------------------------------------------------------------
// mma.sync m16n8k16 row.col f32 += bf16*bf16
// ---------------------------------------------------------------------------
__device__ __forceinline__ void mma_bf16(float d[4],
                                         unsigned a0, unsigned a1,
                                         unsigned a2, unsigned a3,
                                         unsigned b0, unsigned b1) {
    asm volatile(
        "mma.sync.aligned.m16n8k16.row.col.f32.bf16.bf16.f32 "
        "{%0,%1,%2,%3}, {%4,%5,%6,%7}, {%8,%9}, {%0,%1,%2,%3};"
        : "+f"(d[0]), "+f"(d[1]), "+f"(d[2]), "+f"(d[3])
        : "r"(a0), "r"(a1), "r"(a2), "r"(a3), "r"(b0), "r"(b1));
}

// ---------------------------------------------------------------------------
// Kernel 1: reset winner map
// ---------------------------------------------------------------------------
__global__ void init_winner_k(int n) {
    int i = blockIdx.x * blockDim.x + threadIdx.x;
    if (i < n) g_winner[i] = -1;
}

// ---------------------------------------------------------------------------
// Kernel 2: last-pillar-index-wins per BEV cell (deterministic via atomicMax)
// ---------------------------------------------------------------------------
__global__ void winner_k(const int* __restrict__ coors, int P, int B) {
    int p = blockIdx.x * blockDim.x + threadIdx.x;
    if (p >= P) return;
    int b = coors[4 * p + 0];
    int x = coors[4 * p + 1];
    int y = coors[4 * p + 2];
    if ((unsigned)b >= (unsigned)B || (unsigned)x >= XG || (unsigned)y >= YG)
        return;
    atomicMax(&g_winner[(b * XG + x) * YG + y], p);
}

// ---------------------------------------------------------------------------
// Kernel 3: PFN with split-bf16 tensor-core layer 2 + padded-point pruning.
// 256 threads = 8 warps = 8 pillars per block. Warp owns a pillar end-to-end.
// Padded points (n >= npf) have all-zero features -> h1 = ReLU(t1) (constant)
// -> layer-2 column = cvec (global constant, computed once per block in fp32).
// So layer-1 runs only ceil8(npf) points and layer-2 only ceil(npf/8) n-tiles;
// the epilogue max folds cvec in when tiles were skipped.
// ---------------------------------------------------------------------------
#define HS 72   // bf16 stride per row (144 B): (4g+t4) banks, conflict-free

__global__ __launch_bounds__(256) void mlp_k(
    const float* __restrict__ pillars,
    const int*   __restrict__ coors,
    const int*   __restrict__ npoints,
    const float* __restrict__ W1, const float* __restrict__ g1,
    const float* __restrict__ b1, const float* __restrict__ m1,
    const float* __restrict__ v1,
    const float* __restrict__ W2, const float* __restrict__ g2,
    const float* __restrict__ b2, const float* __restrict__ m2,
    const float* __restrict__ v2, int P)
{
    extern __shared__ char smem[];
    __nv_bfloat16* s_w2hi = (__nv_bfloat16*)smem;          // [64][HS]
    __nv_bfloat16* s_w2lo = s_w2hi + 64 * HS;              // [64][HS]
    __nv_bfloat16* s_h1hi = s_w2lo + 64 * HS;              // [8][32][HS]
    __nv_bfloat16* s_h1lo = s_h1hi + 8 * 32 * HS;          // [8][32][HS]
    float* s_s2   = (float*)(s_h1lo + 8 * 32 * HS);        // [64]
    float* s_t2   = s_s2 + 64;                             // [64]
    float* s_rt1  = s_t2 + 64;                             // [64] ReLU(t1)
    float* s_cvec = s_rt1 + 64;                            // [64] const column

    const int tid  = threadIdx.x;
    const int w    = tid >> 5;
    const int lane = tid & 31;
    const int g    = lane >> 2;     // group id (row within fragment)
    const int t4   = lane & 3;      // thread-in-group (col pair)

    // ---- stage W2 as bf16 hi/lo (once per block) ----
    for (int i = tid; i < 4096; i += 256) {
        int o = i >> 6, k = i & 63;
        float wv = W2[i];
        __nv_bfloat16 hi = __float2bfloat16_rn(wv);
        s_w2hi[o * HS + k] = hi;
        s_w2lo[o * HS + k] = __float2bfloat16_rn(wv - __bfloat162float(hi));
    }
    if (tid < 64) {
        float s2v = g2[tid] / sqrtf(v2[tid] + 1e-5f);
        s_s2[tid] = s2v;
        s_t2[tid] = b2[tid] - m2[tid] * s2v;
    } else if (tid < 128) {
        int k = tid - 64;
        float s1 = g1[k] / sqrtf(v1[k] + 1e-5f);
        float t1 = b1[k] - m1[k] * s1;
        s_rt1[k] = fmaxf(t1, 0.0f);
    }
    __syncthreads();

    // ---- cvec[o] = sum_k W2[o,k] * ReLU(t1[k])  (fp32, exact) ----
    if (tid < 64) {
        const float* wrow = &W2[tid * 64];
        float acc = 0.0f;
        #pragma unroll 8
        for (int k = 0; k < 64; ++k) acc = fmaf(__ldg(&wrow[k]), s_rt1[k], acc);
        s_cvec[tid] = acc;
    }
    __syncthreads();   // last block-wide sync

    const int pil = blockIdx.x * 8 + w;
    if (pil >= P) return;

    // ---- features (lane = point) ----
    float4 pt = *(const float4*)&pillars[(pil * 32 + lane) * 4];
    float sx = pt.x, sy = pt.y, sz = pt.z;
    #pragma unroll
    for (int off = 16; off > 0; off >>= 1) {
        sx += __shfl_xor_sync(0xffffffffu, sx, off);
        sy += __shfl_xor_sync(0xffffffffu, sy, off);
        sz += __shfl_xor_sync(0xffffffffu, sz, off);
    }
    const int   npf = npoints[pil];
    const int   nt  = (npf + 7) >> 3;   // n-tiles of 8 points (1..4), warp-uniform
    const int   np8 = nt << 3;          // points to run through layer 1
    const float fn  = (float)npf;
    const float cx = sx / fn, cy = sy / fn, cz = sz / fn;
    const float px = (float)coors[4 * pil + 1] * 0.16f + 0.08f;
    const float py = (float)coors[4 * pil + 2] * 0.16f - 39.6f;
    const float msk = (lane < npf) ? 1.0f : 0.0f;
    float f0 = pt.z * msk;
    float f1 = (pt.x - cx) * msk;
    float f2 = (pt.y - cy) * msk;
    float f3 = (pt.z - cz) * msk;
    float f4 = (pt.x - px) * msk;
    float f5 = (pt.y - py) * msk;

    // ---- layer-1 weights for this lane's 2 channels (folded BN1) ----
    const int c0 = 2 * lane, c1 = c0 + 1;
    float s1a = g1[c0] / sqrtf(v1[c0] + 1e-5f);
    float s1b = g1[c1] / sqrtf(v1[c1] + 1e-5f);
    float t1a = b1[c0] - m1[c0] * s1a;
    float t1b = b1[c1] - m1[c1] * s1b;
    float wa[6], wb[6];
    #pragma unroll
    for (int j = 0; j < 6; ++j) {
        wa[j] = W1[c0 * 6 + j] * s1a;
        wb[j] = W1[c1 * 6 + j] * s1b;
    }

    __nv_bfloat16* h1hi = s_h1hi + w * 32 * HS;
    __nv_bfloat16* h1lo = s_h1lo + w * 32 * HS;

    // ---- layer 1: only the np8 points that feed mma tiles ----
    #pragma unroll 4
    for (int p = 0; p < np8; ++p) {
        float e0 = __shfl_sync(0xffffffffu, f0, p);
        float e1 = __shfl_sync(0xffffffffu, f1, p);
        float e2 = __shfl_sync(0xffffffffu, f2, p);
        float e3 = __shfl_sync(0xffffffffu, f3, p);
        float e4 = __shfl_sync(0xffffffffu, f4, p);
        float e5 = __shfl_sync(0xffffffffu, f5, p);
        float ha = t1a, hb = t1b;
        ha = fmaf(e0, wa[0], ha);  hb = fmaf(e0, wb[0], hb);
        ha = fmaf(e1, wa[1], ha);  hb = fmaf(e1, wb[1], hb);
        ha = fmaf(e2, wa[2], ha);  hb = fmaf(e2, wb[2], hb);
        ha = fmaf(e3, wa[3], ha);  hb = fmaf(e3, wb[3], hb);
        ha = fmaf(e4, wa[4], ha);  hb = fmaf(e4, wb[4], hb);
        ha = fmaf(e5, wa[5], ha);  hb = fmaf(e5, wb[5], hb);
        ha = fmaxf(ha, 0.0f);
        hb = fmaxf(hb, 0.0f);
        __nv_bfloat162 hi2 = __floats2bfloat162_rn(ha, hb);
        float2 hf = __bfloat1622float2(hi2);
        __nv_bfloat162 lo2 = __floats2bfloat162_rn(ha - hf.x, hb - hf.y);
        *(__nv_bfloat162*)&h1hi[p * HS + c0] = hi2;   // bank = lane, CF
        *(__nv_bfloat162*)&h1lo[p * HS + c0] = lo2;
    }
    __syncwarp();

    // ---- layer 2: D[64 o][np8 pt], 4 mtiles x nt ntiles x 4 ktiles ----
    float d[4][4][4];
    #pragma unroll
    for (int m = 0; m < 4; ++m)
        #pragma unroll
        for (int n = 0; n < 4; ++n)
            #pragma unroll
            for (int r = 0; r < 4; ++r) d[m][n][r] = 0.0f;

    #pragma unroll
    for (int kt = 0; kt < 4; ++kt) {
        const int kA = kt * 16 + 2 * t4;
        const int kB = kA + 8;

        unsigned ahi[4][4];
        #pragma unroll
        for (int m = 0; m < 4; ++m) {
            int r0 = (16 * m + g) * HS, r1 = r0 + 8 * HS;
            ahi[m][0] = *(const unsigned*)&s_w2hi[r0 + kA];
            ahi[m][1] = *(const unsigned*)&s_w2hi[r1 + kA];
            ahi[m][2] = *(const unsigned*)&s_w2hi[r0 + kB];
            ahi[m][3] = *(const unsigned*)&s_w2hi[r1 + kB];
        }
        unsigned bhi[4][2], blo[4][2];
        #pragma unroll
        for (int n = 0; n < 4; ++n) {
            if (n < nt) {
                int pr = (8 * n + g) * HS;
                bhi[n][0] = *(const unsigned*)&h1hi[pr + kA];
                bhi[n][1] = *(const unsigned*)&h1hi[pr + kB];
                blo[n][0] = *(const unsigned*)&h1lo[pr + kA];
                blo[n][1] = *(const unsigned*)&h1lo[pr + kB];
            }
        }
        // hi*hi and hi*lo passes
        #pragma unroll
        for (int m = 0; m < 4; ++m)
            #pragma unroll
            for (int n = 0; n < 4; ++n) {
                if (n < nt) {
                    mma_bf16(d[m][n], ahi[m][0], ahi[m][1], ahi[m][2], ahi[m][3],
                             bhi[n][0], bhi[n][1]);
                    mma_bf16(d[m][n], ahi[m][0], ahi[m][1], ahi[m][2], ahi[m][3],
                             blo[n][0], blo[n][1]);
                }
            }
        // lo*hi pass
        unsigned alo[4][4];
        #pragma unroll
        for (int m = 0; m < 4; ++m) {
            int r0 = (16 * m + g) * HS, r1 = r0 + 8 * HS;
            alo[m][0] = *(const unsigned*)&s_w2lo[r0 + kA];
            alo[m][1] = *(const unsigned*)&s_w2lo[r1 + kA];
            alo[m][2] = *(const unsigned*)&s_w2lo[r0 + kB];
            alo[m][3] = *(const unsigned*)&s_w2lo[r1 + kB];
        }
        #pragma unroll
        for (int m = 0; m < 4; ++m)
            #pragma unroll
            for (int n = 0; n < 4; ++n)
                if (n < nt)
                    mma_bf16(d[m][n], alo[m][0], alo[m][1], alo[m][2], alo[m][3],
                             bhi[n][0], bhi[n][1]);
    }

    // ---- epilogue: max&min over computed tiles, fold cvec for skipped ----
    const bool useConst = (np8 < 32);
    #pragma unroll
    for (int m = 0; m < 4; ++m) {
        float mxA = -FLT_MAX, mnA = FLT_MAX;   // row o = 16m + g
        float mxB = -FLT_MAX, mnB = FLT_MAX;   // row o = 16m + g + 8
        #pragma unroll
        for (int n = 0; n < 4; ++n) {
            if (n < nt) {
                mxA = fmaxf(mxA, fmaxf(d[m][n][0], d[m][n][1]));
                mnA = fminf(mnA, fminf(d[m][n][0], d[m][n][1]));
                mxB = fmaxf(mxB, fmaxf(d[m][n][2], d[m][n][3]));
                mnB = fminf(mnB, fminf(d[m][n][2], d[m][n][3]));
            }
        }
        #pragma unroll
        for (int off = 1; off <= 2; off <<= 1) {
            mxA = fmaxf(mxA, __shfl_xor_sync(0xffffffffu, mxA, off));
            mnA = fminf(mnA, __shfl_xor_sync(0xffffffffu, mnA, off));
            mxB = fmaxf(mxB, __shfl_xor_sync(0xffffffffu, mxB, off));
            mnB = fminf(mnB, __shfl_xor_sync(0xffffffffu, mnB, off));
        }
        if (t4 == 0) {
            int oA = 16 * m + g, oB = oA + 8;
            if (useConst) {
                float cA = s_cvec[oA], cB = s_cvec[oB];
                mxA = fmaxf(mxA, cA);  mnA = fminf(mnA, cA);
                mxB = fmaxf(mxB, cB);  mnB = fminf(mnB, cB);
            }
            float sA = s_s2[oA], sB = s_s2[oB];
            float vA = (sA >= 0.0f) ? fmaf(sA, mxA, s_t2[oA])
                                    : fmaf(sA, mnA, s_t2[oA]);
            float vB = (sB >= 0.0f) ? fmaf(sB, mxB, s_t2[oB])
                                    : fmaf(sB, mnB, s_t2[oB]);
            g_pooled[pil * 64 + oA] = vA;
            g_pooled[pil * 64 + oB] = vB;
        }
    }
}

// ---------------------------------------------------------------------------
// Kernel 4: emit pseudo-image (B, C, Y, X). grid = (YG, B), 128 threads.
// ---------------------------------------------------------------------------
__global__ __launch_bounds__(128) void emit_k(float* __restrict__ out) {
    __shared__ int s_wi[XG];
    const int y = blockIdx.x;
    const int b = blockIdx.y;
    for (int x = threadIdx.x; x < XG; x += 128)
        s_wi[x] = g_winner[(b * XG + x) * YG + y];
    __syncthreads();

    const int t = threadIdx.x;
    if (t >= XG / 4) return;   // 108 active threads
    const int x0 = t * 4;

    const float* pp[4];
    bool ok[4];
    #pragma unroll
    for (int i = 0; i < 4; ++i) {
        int wi = s_wi[x0 + i];
        ok[i] = (wi >= 0);
        pp[i] = g_pooled + (ok[i] ? wi : 0) * 64;
    }

    const float4 z4 = make_float4(0.f, 0.f, 0.f, 0.f);
    float* op = out + ((long long)b * CO * YG + y) * XG + x0;
    const long long cstride = (long long)YG * XG;

    #pragma unroll 1
    for (int cq = 0; cq < 16; ++cq) {
        float4 v[4];
        #pragma unroll
        for (int i = 0; i < 4; ++i)
            v[i] = ok[i] ? *(const float4*)(pp[i] + cq * 4) : z4;
        *(float4*)op = make_float4(v[0].x, v[1].x, v[2].x, v[3].x); op += cstride;
        *(float4*)op = make_float4(v[0].y, v[1].y, v[2].y, v[3].y); op += cstride;
        *(float4*)op = make_float4(v[0].z, v[1].z, v[2].z, v[3].z); op += cstride;
        *(float4*)op = make_float4(v[0].w, v[1].w, v[2].w, v[3].w); op += cstride;
    }
}

// ---------------------------------------------------------------------------
// kernel_launch — graph-capturable, allocation-free
// ---------------------------------------------------------------------------
extern "C" void kernel_launch(void* const* d_in, const int* in_sizes, int n_in,
                              void* d_out, int out_size) {
    const float* pillars = (const float*)d_in[0];
    const int*   coors   = (const int*)d_in[1];
    const int*   npts    = (const int*)d_in[2];

    int wbase = (in_sizes[3] == 384) ? 3 : 4;  // skip batch_size slot if present
    const float* W1 = (const float*)d_in[wbase + 0];
    const float* g1 = (const float*)d_in[wbase + 1];
    const float* b1 = (const float*)d_in[wbase + 2];
    const float* m1 = (const float*)d_in[wbase + 3];
    const float* v1 = (const float*)d_in[wbase + 4];
    const float* W2 = (const float*)d_in[wbase + 5];
    const float* g2 = (const float*)d_in[wbase + 6];
    const float* b2 = (const float*)d_in[wbase + 7];
    const float* m2 = (const float*)d_in[wbase + 8];
    const float* v2 = (const float*)d_in[wbase + 9];

    int P = in_sizes[0] / (NPT * 4);
    int B = out_size / (CO * XG * YG);
    if (B > BMAX) B = BMAX;
    if (P > PMAX) P = PMAX;
    int win = B * XG * YG;

    // smem: W2 hi/lo + h1 hi/lo (bf16) + s2/t2/rt1/cvec (fp32)
    const int smemBytes = (2 * 64 * HS + 2 * 8 * 32 * HS) * 2 + 4 * 64 * 4;
    cudaFuncSetAttribute(mlp_k, cudaFuncAttributeMaxDynamicSharedMemorySize,
                         smemBytes);

    init_winner_k<<<(win + 255) / 256, 256>>>(win);
    winner_k<<<(P + 255) / 256, 256>>>(coors, P, B);
    mlp_k<<<(P + 7) / 8, 256, smemBytes>>>(pillars, coors, npts,
                                           W1, g1, b1, m1, v1,
                                           W2, g2, b2, m2, v2, P);
    emit_k<<<dim3(YG, B), 128>>>((float*)d_out);
}

// round 12
// speedup vs baseline: 1.0238x; 1.0238x over previous
#include <cuda_runtime.h>
#include <cuda_bf16.h>
#include <math.h>
#include <float.h>

#define XG 432
#define YG 496
#define CO 64
#define NPT 32
#define PMAX 64000
#define BMAX 4

// Scratch (no allocations allowed anywhere)
__device__ int   g_winner[BMAX * XG * YG];
__device__ float g_pooled[PMAX * CO];

// ---------------------------------------------------------------------------
// mma.sync m16n8k16 row.col f32 += bf16*bf16
// ---------------------------------------------------------------------------
__device__ __forceinline__ void mma_bf16(float d[4],
                                         unsigned a0, unsigned a1,
                                         unsigned a2, unsigned a3,
                                         unsigned b0, unsigned b1) {
    asm volatile(
        "mma.sync.aligned.m16n8k16.row.col.f32.bf16.bf16.f32 "
        "{%0,%1,%2,%3}, {%4,%5,%6,%7}, {%8,%9}, {%0,%1,%2,%3};"
        : "+f"(d[0]), "+f"(d[1]), "+f"(d[2]), "+f"(d[3])
        : "r"(a0), "r"(a1), "r"(a2), "r"(a3), "r"(b0), "r"(b1));
}

// ---------------------------------------------------------------------------
// Kernel 1: reset winner map
// ---------------------------------------------------------------------------
__global__ void init_winner_k(int n) {
    int i = blockIdx.x * blockDim.x + threadIdx.x;
    if (i < n) g_winner[i] = -1;
}

// ---------------------------------------------------------------------------
// Kernel 2: last-pillar-index-wins per BEV cell (deterministic via atomicMax)
// ---------------------------------------------------------------------------
__global__ void winner_k(const int* __restrict__ coors, int P, int B) {
    int p = blockIdx.x * blockDim.x + threadIdx.x;
    if (p >= P) return;
    int b = coors[4 * p + 0];
    int x = coors[4 * p + 1];
    int y = coors[4 * p + 2];
    if ((unsigned)b >= (unsigned)B || (unsigned)x >= XG || (unsigned)y >= YG)
        return;
    atomicMax(&g_winner[(b * XG + x) * YG + y], p);
}

#define HS 72   // bf16 stride per row (144 B): conflict-free fragment loads

// ---------------------------------------------------------------------------
// Templated layer-2 GEMM + epilogue. NT = number of 8-point n-tiles (1..4).
// ALL loop bounds compile-time -> fully unrolled, no conditional fragments.
// ---------------------------------------------------------------------------
template<int NT>
__device__ __forceinline__ void gemm_epi(
    const __nv_bfloat16* __restrict__ s_w2hi,
    const __nv_bfloat16* __restrict__ s_w2lo,
    const __nv_bfloat16* __restrict__ h1hi,
    const __nv_bfloat16* __restrict__ h1lo,
    const float* __restrict__ s_s2, const float* __restrict__ s_t2,
    const float* __restrict__ s_cvec,
    int g, int t4, int pil)
{
    float d[4][NT][4];
    #pragma unroll
    for (int m = 0; m < 4; ++m)
        #pragma unroll
        for (int n = 0; n < NT; ++n)
            #pragma unroll
            for (int r = 0; r < 4; ++r) d[m][n][r] = 0.0f;

    #pragma unroll
    for (int kt = 0; kt < 4; ++kt) {
        const int kA = kt * 16 + 2 * t4;
        const int kB = kA + 8;

        unsigned ahi[4][4];
        #pragma unroll
        for (int m = 0; m < 4; ++m) {
            int r0 = (16 * m + g) * HS, r1 = r0 + 8 * HS;
            ahi[m][0] = *(const unsigned*)&s_w2hi[r0 + kA];
            ahi[m][1] = *(const unsigned*)&s_w2hi[r1 + kA];
            ahi[m][2] = *(const unsigned*)&s_w2hi[r0 + kB];
            ahi[m][3] = *(const unsigned*)&s_w2hi[r1 + kB];
        }
        unsigned bhi[NT][2], blo[NT][2];
        #pragma unroll
        for (int n = 0; n < NT; ++n) {
            int pr = (8 * n + g) * HS;
            bhi[n][0] = *(const unsigned*)&h1hi[pr + kA];
            bhi[n][1] = *(const unsigned*)&h1hi[pr + kB];
            blo[n][0] = *(const unsigned*)&h1lo[pr + kA];
            blo[n][1] = *(const unsigned*)&h1lo[pr + kB];
        }
        #pragma unroll
        for (int m = 0; m < 4; ++m)
            #pragma unroll
            for (int n = 0; n < NT; ++n) {
                mma_bf16(d[m][n], ahi[m][0], ahi[m][1], ahi[m][2], ahi[m][3],
                         bhi[n][0], bhi[n][1]);
                mma_bf16(d[m][n], ahi[m][0], ahi[m][1], ahi[m][2], ahi[m][3],
                         blo[n][0], blo[n][1]);
            }
        unsigned alo[4][4];
        #pragma unroll
        for (int m = 0; m < 4; ++m) {
            int r0 = (16 * m + g) * HS, r1 = r0 + 8 * HS;
            alo[m][0] = *(const unsigned*)&s_w2lo[r0 + kA];
            alo[m][1] = *(const unsigned*)&s_w2lo[r1 + kA];
            alo[m][2] = *(const unsigned*)&s_w2lo[r0 + kB];
            alo[m][3] = *(const unsigned*)&s_w2lo[r1 + kB];
        }
        #pragma unroll
        for (int m = 0; m < 4; ++m)
            #pragma unroll
            for (int n = 0; n < NT; ++n)
                mma_bf16(d[m][n], alo[m][0], alo[m][1], alo[m][2], alo[m][3],
                         bhi[n][0], bhi[n][1]);
    }

    // epilogue: max&min over computed tiles; skipped tiles == cvec column
    #pragma unroll
    for (int m = 0; m < 4; ++m) {
        float mxA = -FLT_MAX, mnA = FLT_MAX;   // row o = 16m + g
        float mxB = -FLT_MAX, mnB = FLT_MAX;   // row o = 16m + g + 8
        #pragma unroll
        for (int n = 0; n < NT; ++n) {
            mxA = fmaxf(mxA, fmaxf(d[m][n][0], d[m][n][1]));
            mnA = fminf(mnA, fminf(d[m][n][0], d[m][n][1]));
            mxB = fmaxf(mxB, fmaxf(d[m][n][2], d[m][n][3]));
            mnB = fminf(mnB, fminf(d[m][n][2], d[m][n][3]));
        }
        #pragma unroll
        for (int off = 1; off <= 2; off <<= 1) {
            mxA = fmaxf(mxA, __shfl_xor_sync(0xffffffffu, mxA, off));
            mnA = fminf(mnA, __shfl_xor_sync(0xffffffffu, mnA, off));
            mxB = fmaxf(mxB, __shfl_xor_sync(0xffffffffu, mxB, off));
            mnB = fminf(mnB, __shfl_xor_sync(0xffffffffu, mnB, off));
        }
        if (t4 == 0) {
            int oA = 16 * m + g, oB = oA + 8;
            if (NT < 4) {   // compile-time: fold constant (padded) column
                float cA = s_cvec[oA], cB = s_cvec[oB];
                mxA = fmaxf(mxA, cA);  mnA = fminf(mnA, cA);
                mxB = fmaxf(mxB, cB);  mnB = fminf(mnB, cB);
            }
            float sA = s_s2[oA], sB = s_s2[oB];
            float vA = (sA >= 0.0f) ? fmaf(sA, mxA, s_t2[oA])
                                    : fmaf(sA, mnA, s_t2[oA]);
            float vB = (sB >= 0.0f) ? fmaf(sB, mxB, s_t2[oB])
                                    : fmaf(sB, mnB, s_t2[oB]);
            g_pooled[pil * 64 + oA] = vA;
            g_pooled[pil * 64 + oB] = vB;
        }
    }
}

// ---------------------------------------------------------------------------
// Kernel 3: PFN, split-bf16 tensor-core layer 2, NT-specialized pruning.
// 256 threads = 8 warps = 8 pillars per block; warp owns a pillar end-to-end.
// ---------------------------------------------------------------------------
__global__ __launch_bounds__(256) void mlp_k(
    const float* __restrict__ pillars,
    const int*   __restrict__ coors,
    const int*   __restrict__ npoints,
    const float* __restrict__ W1, const float* __restrict__ g1,
    const float* __restrict__ b1, const float* __restrict__ m1,
    const float* __restrict__ v1,
    const float* __restrict__ W2, const float* __restrict__ g2,
    const float* __restrict__ b2, const float* __restrict__ m2,
    const float* __restrict__ v2, int P)
{
    extern __shared__ char smem[];
    __nv_bfloat16* s_w2hi = (__nv_bfloat16*)smem;          // [64][HS]
    __nv_bfloat16* s_w2lo = s_w2hi + 64 * HS;              // [64][HS]
    __nv_bfloat16* s_h1hi = s_w2lo + 64 * HS;              // [8][32][HS]
    __nv_bfloat16* s_h1lo = s_h1hi + 8 * 32 * HS;          // [8][32][HS]
    float* s_s2   = (float*)(s_h1lo + 8 * 32 * HS);        // [64]
    float* s_t2   = s_s2 + 64;                             // [64]
    float* s_rt1  = s_t2 + 64;                             // [64] ReLU(t1)
    float* s_cvec = s_rt1 + 64;                            // [64] const column

    const int tid  = threadIdx.x;
    const int w    = tid >> 5;
    const int lane = tid & 31;
    const int g    = lane >> 2;
    const int t4   = lane & 3;

    // ---- stage W2 as bf16 hi/lo (once per block) ----
    for (int i = tid; i < 4096; i += 256) {
        int o = i >> 6, k = i & 63;
        float wv = W2[i];
        __nv_bfloat16 hi = __float2bfloat16_rn(wv);
        s_w2hi[o * HS + k] = hi;
        s_w2lo[o * HS + k] = __float2bfloat16_rn(wv - __bfloat162float(hi));
    }
    if (tid < 64) {
        float s2v = g2[tid] / sqrtf(v2[tid] + 1e-5f);
        s_s2[tid] = s2v;
        s_t2[tid] = b2[tid] - m2[tid] * s2v;
    } else if (tid < 128) {
        int k = tid - 64;
        float s1 = g1[k] / sqrtf(v1[k] + 1e-5f);
        float t1 = b1[k] - m1[k] * s1;
        s_rt1[k] = fmaxf(t1, 0.0f);
    }
    __syncthreads();

    // ---- cvec[o] = sum_k W2[o,k] * ReLU(t1[k])  (fp32, exact) ----
    if (tid < 64) {
        const float* wrow = &W2[tid * 64];
        float acc = 0.0f;
        #pragma unroll 8
        for (int k = 0; k < 64; ++k) acc = fmaf(__ldg(&wrow[k]), s_rt1[k], acc);
        s_cvec[tid] = acc;
    }
    __syncthreads();   // last block-wide sync

    const int pil = blockIdx.x * 8 + w;
    if (pil >= P) return;

    // ---- features (lane = point) ----
    float4 pt = *(const float4*)&pillars[(pil * 32 + lane) * 4];
    float sx = pt.x, sy = pt.y, sz = pt.z;
    #pragma unroll
    for (int off = 16; off > 0; off >>= 1) {
        sx += __shfl_xor_sync(0xffffffffu, sx, off);
        sy += __shfl_xor_sync(0xffffffffu, sy, off);
        sz += __shfl_xor_sync(0xffffffffu, sz, off);
    }
    const int   npf = npoints[pil];
    const int   nt  = (npf + 7) >> 3;   // 1..4, warp-uniform
    const float fn  = (float)npf;
    const float cx = sx / fn, cy = sy / fn, cz = sz / fn;
    const float px = (float)coors[4 * pil + 1] * 0.16f + 0.08f;
    const float py = (float)coors[4 * pil + 2] * 0.16f - 39.6f;
    const float msk = (lane < npf) ? 1.0f : 0.0f;
    float f0 = pt.z * msk;
    float f1 = (pt.x - cx) * msk;
    float f2 = (pt.y - cy) * msk;
    float f3 = (pt.z - cz) * msk;
    float f4 = (pt.x - px) * msk;
    float f5 = (pt.y - py) * msk;

    // ---- layer-1 weights for this lane's 2 channels (folded BN1) ----
    const int c0 = 2 * lane, c1 = c0 + 1;
    float s1a = g1[c0] / sqrtf(v1[c0] + 1e-5f);
    float s1b = g1[c1] / sqrtf(v1[c1] + 1e-5f);
    float t1a = b1[c0] - m1[c0] * s1a;
    float t1b = b1[c1] - m1[c1] * s1b;
    float wa[6], wb[6];
    #pragma unroll
    for (int j = 0; j < 6; ++j) {
        wa[j] = W1[c0 * 6 + j] * s1a;
        wb[j] = W1[c1 * 6 + j] * s1b;
    }

    __nv_bfloat16* h1hi = s_h1hi + w * 32 * HS;
    __nv_bfloat16* h1lo = s_h1lo + w * 32 * HS;

    // ---- layer 1: nt tiles of 8 points, inner loop fully unrolled ----
    for (int pt8 = 0; pt8 < nt; ++pt8) {
        #pragma unroll
        for (int j = 0; j < 8; ++j) {
            int p = pt8 * 8 + j;                 // register shfl lane: OK
            float e0 = __shfl_sync(0xffffffffu, f0, p);
            float e1 = __shfl_sync(0xffffffffu, f1, p);
            float e2 = __shfl_sync(0xffffffffu, f2, p);
            float e3 = __shfl_sync(0xffffffffu, f3, p);
            float e4 = __shfl_sync(0xffffffffu, f4, p);
            float e5 = __shfl_sync(0xffffffffu, f5, p);
            float ha = t1a, hb = t1b;
            ha = fmaf(e0, wa[0], ha);  hb = fmaf(e0, wb[0], hb);
            ha = fmaf(e1, wa[1], ha);  hb = fmaf(e1, wb[1], hb);
            ha = fmaf(e2, wa[2], ha);  hb = fmaf(e2, wb[2], hb);
            ha = fmaf(e3, wa[3], ha);  hb = fmaf(e3, wb[3], hb);
            ha = fmaf(e4, wa[4], ha);  hb = fmaf(e4, wb[4], hb);
            ha = fmaf(e5, wa[5], ha);  hb = fmaf(e5, wb[5], hb);
            ha = fmaxf(ha, 0.0f);
            hb = fmaxf(hb, 0.0f);
            __nv_bfloat162 hi2 = __floats2bfloat162_rn(ha, hb);
            float2 hf = __bfloat1622float2(hi2);
            __nv_bfloat162 lo2 = __floats2bfloat162_rn(ha - hf.x, hb - hf.y);
            *(__nv_bfloat162*)&h1hi[p * HS + c0] = hi2;
            *(__nv_bfloat162*)&h1lo[p * HS + c0] = lo2;
        }
    }
    __syncwarp();

    // ---- layer 2 + epilogue, specialized on nt ----
    switch (nt) {
        case 1: gemm_epi<1>(s_w2hi, s_w2lo, h1hi, h1lo, s_s2, s_t2, s_cvec,
                            g, t4, pil); break;
        case 2: gemm_epi<2>(s_w2hi, s_w2lo, h1hi, h1lo, s_s2, s_t2, s_cvec,
                            g, t4, pil); break;
        case 3: gemm_epi<3>(s_w2hi, s_w2lo, h1hi, h1lo, s_s2, s_t2, s_cvec,
                            g, t4, pil); break;
        default: gemm_epi<4>(s_w2hi, s_w2lo, h1hi, h1lo, s_s2, s_t2, s_cvec,
                             g, t4, pil); break;
    }
}

// ---------------------------------------------------------------------------
// Kernel 4: emit pseudo-image (B, C, Y, X). grid = (YG, 4*B), 128 threads.
// Each block handles 4 of the 16 c-quads for one (b, y) row -> 4x more TLP
// to hide L2 gather latency. Coalesced STG.128 stores.
// ---------------------------------------------------------------------------
__global__ __launch_bounds__(128) void emit_k(float* __restrict__ out) {
    __shared__ int s_wi[XG];
    const int y    = blockIdx.x;
    const int b    = blockIdx.y >> 2;
    const int part = blockIdx.y & 3;
    for (int x = threadIdx.x; x < XG; x += 128)
        s_wi[x] = g_winner[(b * XG + x) * YG + y];
    __syncthreads();

    const int t = threadIdx.x;
    if (t >= XG / 4) return;   // 108 active threads
    const int x0 = t * 4;

    const float* pp[4];
    bool ok[4];
    #pragma unroll
    for (int i = 0; i < 4; ++i) {
        int wi = s_wi[x0 + i];
        ok[i] = (wi >= 0);
        pp[i] = g_pooled + (ok[i] ? wi : 0) * 64;
    }

    const float4 z4 = make_float4(0.f, 0.f, 0.f, 0.f);
    const long long cstride = (long long)YG * XG;
    float* op = out + ((long long)b * CO + part * 16) * cstride
                    + (long long)y * XG + x0;

    #pragma unroll
    for (int cq = part * 4; cq < part * 4 + 4; ++cq) {
        float4 v[4];
        #pragma unroll
        for (int i = 0; i < 4; ++i)
            v[i] = ok[i] ? *(const float4*)(pp[i] + cq * 4) : z4;
        *(float4*)op = make_float4(v[0].x, v[1].x, v[2].x, v[3].x); op += cstride;
        *(float4*)op = make_float4(v[0].y, v[1].y, v[2].y, v[3].y); op += cstride;
        *(float4*)op = make_float4(v[0].z, v[1].z, v[2].z, v[3].z); op += cstride;
        *(float4*)op = make_float4(v[0].w, v[1].w, v[2].w, v[3].w); op += cstride;
    }
}

// ---------------------------------------------------------------------------
// kernel_launch — graph-capturable, allocation-free
// ---------------------------------------------------------------------------
extern "C" void kernel_launch(void* const* d_in, const int* in_sizes, int n_in,
                              void* d_out, int out_size) {
    const float* pillars = (const float*)d_in[0];
    const int*   coors   = (const int*)d_in[1];
    const int*   npts    = (const int*)d_in[2];

    int wbase = (in_sizes[3] == 384) ? 3 : 4;  // skip batch_size slot if present
    const float* W1 = (const float*)d_in[wbase + 0];
    const float* g1 = (const float*)d_in[wbase + 1];
    const float* b1 = (const float*)d_in[wbase + 2];
    const float* m1 = (const float*)d_in[wbase + 3];
    const float* v1 = (const float*)d_in[wbase + 4];
    const float* W2 = (const float*)d_in[wbase + 5];
    const float* g2 = (const float*)d_in[wbase + 6];
    const float* b2 = (const float*)d_in[wbase + 7];
    const float* m2 = (const float*)d_in[wbase + 8];
    const float* v2 = (const float*)d_in[wbase + 9];

    int P = in_sizes[0] / (NPT * 4);
    int B = out_size / (CO * XG * YG);
    if (B > BMAX) B = BMAX;
    if (P > PMAX) P = PMAX;
    int win = B * XG * YG;

    const int smemBytes = (2 * 64 * HS + 2 * 8 * 32 * HS) * 2 + 4 * 64 * 4;
    cudaFuncSetAttribute(mlp_k, cudaFuncAttributeMaxDynamicSharedMemorySize,
                         smemBytes);

    init_winner_k<<<(win + 255) / 256, 256>>>(win);
    winner_k<<<(P + 255) / 256, 256>>>(coors, P, B);
    mlp_k<<<(P + 7) / 8, 256, smemBytes>>>(pillars, coors, npts,
                                           W1, g1, b1, m1, v1,
                                           W2, g2, b2, m2, v2, P);
    emit_k<<<dim3(YG, 4 * B), 128>>>((float*)d_out);
}

// round 14
// speedup vs baseline: 1.1099x; 1.0841x over previous
#include <cuda_runtime.h>
#include <cuda_bf16.h>
#include <math.h>
#include <float.h>

#define XG 432
#define YG 496
#define CO 64
#define PMAX 64000
#define BMAX 4
#define HS 72   // bf16 stride per row (144 B): conflict-free fragment loads

// Scratch (no allocations allowed anywhere)
__device__ int   g_winner[BMAX * XG * YG];
__device__ float g_pooled[PMAX * CO];
__device__ int   g_bucket[4 * PMAX];
__device__ int   g_cnt[4];

// ---------------------------------------------------------------------------
// mma.sync m16n8k16 row.col f32 += bf16*bf16
// ---------------------------------------------------------------------------
__device__ __forceinline__ void mma_bf16(float d[4],
                                         unsigned a0, unsigned a1,
                                         unsigned a2, unsigned a3,
                                         unsigned b0, unsigned b1) {
    asm volatile(
        "mma.sync.aligned.m16n8k16.row.col.f32.bf16.bf16.f32 "
        "{%0,%1,%2,%3}, {%4,%5,%6,%7}, {%8,%9}, {%0,%1,%2,%3};"
        : "+f"(d[0]), "+f"(d[1]), "+f"(d[2]), "+f"(d[3])
        : "r"(a0), "r"(a1), "r"(a2), "r"(a3), "r"(b0), "r"(b1));
}

// ---------------------------------------------------------------------------
// Kernel 1: reset winner map + bucket counters
// ---------------------------------------------------------------------------
__global__ void init_winner_k(int n) {
    int i = blockIdx.x * blockDim.x + threadIdx.x;
    if (i < n) g_winner[i] = -1;
    if (i < 4) g_cnt[i] = 0;
}

// ---------------------------------------------------------------------------
// Kernel 2: winner map (atomicMax, last-pillar-wins) + NT bucket scatter
// ---------------------------------------------------------------------------
__global__ void winner_k(const int* __restrict__ coors,
                         const int* __restrict__ npoints, int P, int B) {
    int p = blockIdx.x * blockDim.x + threadIdx.x;
    if (p >= P) return;
    int b = coors[4 * p + 0];
    int x = coors[4 * p + 1];
    int y = coors[4 * p + 2];
    if ((unsigned)b < (unsigned)B && (unsigned)x < XG && (unsigned)y < YG)
        atomicMax(&g_winner[(b * XG + x) * YG + y], p);
    int nt = (npoints[p] + 7) >> 3;          // 1..4
    if (nt < 1) nt = 1;
    if (nt > 4) nt = 4;
    int slot = atomicAdd(&g_cnt[nt - 1], 1);
    g_bucket[(nt - 1) * PMAX + slot] = p;
}

// ---------------------------------------------------------------------------
// Kernel 3 (x4 instances): PFN specialized on NT = #8-point tiles.
// 256 threads = 8 warps = 8 pillars per block (from bucket NT-1).
// Straight-line code per kernel: no NT divergence, one instance in I-cache.
// Split-bf16 3-pass mma (hi*hi + hi*lo + lo*hi); skipped padded tiles are the
// constant column cvec (fp32), folded in the epilogue when NT<4.
// ---------------------------------------------------------------------------
template<int NT>
__global__ __launch_bounds__(256) void mlp_nt_k(
    const float* __restrict__ pillars,
    const int*   __restrict__ coors,
    const int*   __restrict__ npoints,
    const float* __restrict__ W1, const float* __restrict__ g1,
    const float* __restrict__ b1, const float* __restrict__ m1,
    const float* __restrict__ v1,
    const float* __restrict__ W2, const float* __restrict__ g2,
    const float* __restrict__ b2, const float* __restrict__ m2,
    const float* __restrict__ v2)
{
    const int cnt = g_cnt[NT - 1];
    if (blockIdx.x * 8 >= cnt) return;

    extern __shared__ char smem[];
    __nv_bfloat16* s_w2hi = (__nv_bfloat16*)smem;          // [64][HS]
    __nv_bfloat16* s_w2lo = s_w2hi + 64 * HS;              // [64][HS]
    __nv_bfloat16* s_h1hi = s_w2lo + 64 * HS;              // [8][NT*8][HS]
    __nv_bfloat16* s_h1lo = s_h1hi + 8 * NT * 8 * HS;      // [8][NT*8][HS]
    float* s_s2   = (float*)(s_h1lo + 8 * NT * 8 * HS);    // [64]
    float* s_t2   = s_s2 + 64;                             // [64]
    float* s_cvec = s_t2 + 64;                             // [64]
    float* s_rt1  = s_cvec + 64;                           // [64]

    const int tid  = threadIdx.x;
    const int w    = tid >> 5;
    const int lane = tid & 31;
    const int g    = lane >> 2;
    const int t4   = lane & 3;

    // ---- stage W2 as bf16 hi/lo ----
    for (int i = tid; i < 4096; i += 256) {
        int o = i >> 6, k = i & 63;
        float wv = W2[i];
        __nv_bfloat16 hi = __float2bfloat16_rn(wv);
        s_w2hi[o * HS + k] = hi;
        s_w2lo[o * HS + k] = __float2bfloat16_rn(wv - __bfloat162float(hi));
    }
    if (tid < 64) {
        float s2v = g2[tid] / sqrtf(v2[tid] + 1e-5f);
        s_s2[tid] = s2v;
        s_t2[tid] = b2[tid] - m2[tid] * s2v;
    } else if (NT < 4 && tid < 128) {
        int k = tid - 64;
        float s1 = g1[k] / sqrtf(v1[k] + 1e-5f);
        float t1 = b1[k] - m1[k] * s1;
        s_rt1[k] = fmaxf(t1, 0.0f);
    }
    if (NT < 4) {
        __syncthreads();
        // cvec[o] = sum_k W2[o,k] * ReLU(t1[k])  (fp32, exact)
        if (tid < 64) {
            const float* wrow = &W2[tid * 64];
            float acc = 0.0f;
            #pragma unroll 8
            for (int k = 0; k < 64; ++k)
                acc = fmaf(__ldg(&wrow[k]), s_rt1[k], acc);
            s_cvec[tid] = acc;
        }
    }
    __syncthreads();

    const int idx   = blockIdx.x * 8 + w;
    const bool valid = (idx < cnt);
    const int pil   = valid ? g_bucket[(NT - 1) * PMAX + idx] : 0;

    __nv_bfloat16* h1hi = s_h1hi + w * (NT * 8) * HS;
    __nv_bfloat16* h1lo = s_h1lo + w * (NT * 8) * HS;

    if (valid) {
        // ---- features (lane = point) ----
        float4 pt = *(const float4*)&pillars[(pil * 32 + lane) * 4];
        float sx = pt.x, sy = pt.y, sz = pt.z;
        #pragma unroll
        for (int off = 16; off > 0; off >>= 1) {
            sx += __shfl_xor_sync(0xffffffffu, sx, off);
            sy += __shfl_xor_sync(0xffffffffu, sy, off);
            sz += __shfl_xor_sync(0xffffffffu, sz, off);
        }
        const int   npf = npoints[pil];
        const float fn  = (float)npf;
        const float cx = sx / fn, cy = sy / fn, cz = sz / fn;
        const float px = (float)coors[4 * pil + 1] * 0.16f + 0.08f;
        const float py = (float)coors[4 * pil + 2] * 0.16f - 39.6f;
        const float msk = (lane < npf) ? 1.0f : 0.0f;
        float f0 = pt.z * msk;
        float f1 = (pt.x - cx) * msk;
        float f2 = (pt.y - cy) * msk;
        float f3 = (pt.z - cz) * msk;
        float f4 = (pt.x - px) * msk;
        float f5 = (pt.y - py) * msk;

        // ---- layer-1 weights for this lane's 2 channels (folded BN1) ----
        const int c0 = 2 * lane, c1 = c0 + 1;
        float s1a = g1[c0] / sqrtf(v1[c0] + 1e-5f);
        float s1b = g1[c1] / sqrtf(v1[c1] + 1e-5f);
        float t1a = b1[c0] - m1[c0] * s1a;
        float t1b = b1[c1] - m1[c1] * s1b;
        float wa[6], wb[6];
        #pragma unroll
        for (int j = 0; j < 6; ++j) {
            wa[j] = W1[c0 * 6 + j] * s1a;
            wb[j] = W1[c1 * 6 + j] * s1b;
        }

        // ---- layer 1: NT*8 points, fully unrolled ----
        #pragma unroll
        for (int p = 0; p < NT * 8; ++p) {
            float e0 = __shfl_sync(0xffffffffu, f0, p);
            float e1 = __shfl_sync(0xffffffffu, f1, p);
            float e2 = __shfl_sync(0xffffffffu, f2, p);
            float e3 = __shfl_sync(0xffffffffu, f3, p);
            float e4 = __shfl_sync(0xffffffffu, f4, p);
            float e5 = __shfl_sync(0xffffffffu, f5, p);
            float ha = t1a, hb = t1b;
            ha = fmaf(e0, wa[0], ha);  hb = fmaf(e0, wb[0], hb);
            ha = fmaf(e1, wa[1], ha);  hb = fmaf(e1, wb[1], hb);
            ha = fmaf(e2, wa[2], ha);  hb = fmaf(e2, wb[2], hb);
            ha = fmaf(e3, wa[3], ha);  hb = fmaf(e3, wb[3], hb);
            ha = fmaf(e4, wa[4], ha);  hb = fmaf(e4, wb[4], hb);
            ha = fmaf(e5, wa[5], ha);  hb = fmaf(e5, wb[5], hb);
            ha = fmaxf(ha, 0.0f);
            hb = fmaxf(hb, 0.0f);
            __nv_bfloat162 hi2 = __floats2bfloat162_rn(ha, hb);
            float2 hf = __bfloat1622float2(hi2);
            __nv_bfloat162 lo2 = __floats2bfloat162_rn(ha - hf.x, hb - hf.y);
            *(__nv_bfloat162*)&h1hi[p * HS + c0] = hi2;
            *(__nv_bfloat162*)&h1lo[p * HS + c0] = lo2;
        }
    }
    __syncwarp();

    // ---- layer 2: D[64 o][NT*8 pt], 4 mtiles x NT ntiles x 4 ktiles ----
    float d[4][NT][4];
    #pragma unroll
    for (int m = 0; m < 4; ++m)
        #pragma unroll
        for (int n = 0; n < NT; ++n)
            #pragma unroll
            for (int r = 0; r < 4; ++r) d[m][n][r] = 0.0f;

    #pragma unroll
    for (int kt = 0; kt < 4; ++kt) {
        const int kA = kt * 16 + 2 * t4;
        const int kB = kA + 8;

        unsigned ahi[4][4];
        #pragma unroll
        for (int m = 0; m < 4; ++m) {
            int r0 = (16 * m + g) * HS, r1 = r0 + 8 * HS;
            ahi[m][0] = *(const unsigned*)&s_w2hi[r0 + kA];
            ahi[m][1] = *(const unsigned*)&s_w2hi[r1 + kA];
            ahi[m][2] = *(const unsigned*)&s_w2hi[r0 + kB];
            ahi[m][3] = *(const unsigned*)&s_w2hi[r1 + kB];
        }
        unsigned bhi[NT][2], blo[NT][2];
        #pragma unroll
        for (int n = 0; n < NT; ++n) {
            int pr = (8 * n + g) * HS;
            bhi[n][0] = *(const unsigned*)&h1hi[pr + kA];
            bhi[n][1] = *(const unsigned*)&h1hi[pr + kB];
            blo[n][0] = *(const unsigned*)&h1lo[pr + kA];
            blo[n][1] = *(const unsigned*)&h1lo[pr + kB];
        }
        #pragma unroll
        for (int m = 0; m < 4; ++m)
            #pragma unroll
            for (int n = 0; n < NT; ++n) {
                mma_bf16(d[m][n], ahi[m][0], ahi[m][1], ahi[m][2], ahi[m][3],
                         bhi[n][0], bhi[n][1]);
                mma_bf16(d[m][n], ahi[m][0], ahi[m][1], ahi[m][2], ahi[m][3],
                         blo[n][0], blo[n][1]);
            }
        unsigned alo[4][4];
        #pragma unroll
        for (int m = 0; m < 4; ++m) {
            int r0 = (16 * m + g) * HS, r1 = r0 + 8 * HS;
            alo[m][0] = *(const unsigned*)&s_w2lo[r0 + kA];
            alo[m][1] = *(const unsigned*)&s_w2lo[r1 + kA];
            alo[m][2] = *(const unsigned*)&s_w2lo[r0 + kB];
            alo[m][3] = *(const unsigned*)&s_w2lo[r1 + kB];
        }
        #pragma unroll
        for (int m = 0; m < 4; ++m)
            #pragma unroll
            for (int n = 0; n < NT; ++n)
                mma_bf16(d[m][n], alo[m][0], alo[m][1], alo[m][2], alo[m][3],
                         bhi[n][0], bhi[n][1]);
    }

    // ---- epilogue: max&min over computed tiles; cvec for skipped tiles ----
    #pragma unroll
    for (int m = 0; m < 4; ++m) {
        float mxA = -FLT_MAX, mnA = FLT_MAX;   // row o = 16m + g
        float mxB = -FLT_MAX, mnB = FLT_MAX;   // row o = 16m + g + 8
        #pragma unroll
        for (int n = 0; n < NT; ++n) {
            mxA = fmaxf(mxA, fmaxf(d[m][n][0], d[m][n][1]));
            mnA = fminf(mnA, fminf(d[m][n][0], d[m][n][1]));
            mxB = fmaxf(mxB, fmaxf(d[m][n][2], d[m][n][3]));
            mnB = fminf(mnB, fminf(d[m][n][2], d[m][n][3]));
        }
        #pragma unroll
        for (int off = 1; off <= 2; off <<= 1) {
            mxA = fmaxf(mxA, __shfl_xor_sync(0xffffffffu, mxA, off));
            mnA = fminf(mnA, __shfl_xor_sync(0xffffffffu, mnA, off));
            mxB = fmaxf(mxB, __shfl_xor_sync(0xffffffffu, mxB, off));
            mnB = fminf(mnB, __shfl_xor_sync(0xffffffffu, mnB, off));
        }
        if (t4 == 0 && valid) {
            int oA = 16 * m + g, oB = oA + 8;
            if (NT < 4) {   // compile-time: fold constant (padded) column
                float cA = s_cvec[oA], cB = s_cvec[oB];
                mxA = fmaxf(mxA, cA);  mnA = fminf(mnA, cA);
                mxB = fmaxf(mxB, cB);  mnB = fminf(mnB, cB);
            }
            float sA = s_s2[oA], sB = s_s2[oB];
            float vA = (sA >= 0.0f) ? fmaf(sA, mxA, s_t2[oA])
                                    : fmaf(sA, mnA, s_t2[oA]);
            float vB = (sB >= 0.0f) ? fmaf(sB, mxB, s_t2[oB])
                                    : fmaf(sB, mnB, s_t2[oB]);
            g_pooled[pil * 64 + oA] = vA;
            g_pooled[pil * 64 + oB] = vB;
        }
    }
}

// ---------------------------------------------------------------------------
// Kernel 4: emit pseudo-image (B, C, Y, X). grid = (YG, 4*B), 128 threads.
// ---------------------------------------------------------------------------
__global__ __launch_bounds__(128) void emit_k(float* __restrict__ out) {
    __shared__ int s_wi[XG];
    const int y    = blockIdx.x;
    const int b    = blockIdx.y >> 2;
    const int part = blockIdx.y & 3;
    for (int x = threadIdx.x; x < XG; x += 128)
        s_wi[x] = g_winner[(b * XG + x) * YG + y];
    __syncthreads();

    const int t = threadIdx.x;
    if (t >= XG / 4) return;   // 108 active threads
    const int x0 = t * 4;

    const float* pp[4];
    bool ok[4];
    #pragma unroll
    for (int i = 0; i < 4; ++i) {
        int wi = s_wi[x0 + i];
        ok[i] = (wi >= 0);
        pp[i] = g_pooled + (ok[i] ? wi : 0) * 64;
    }

    const float4 z4 = make_float4(0.f, 0.f, 0.f, 0.f);
    const long long cstride = (long long)YG * XG;
    float* op = out + ((long long)b * CO + part * 16) * cstride
                    + (long long)y * XG + x0;

    #pragma unroll
    for (int cq = part * 4; cq < part * 4 + 4; ++cq) {
        float4 v[4];
        #pragma unroll
        for (int i = 0; i < 4; ++i)
            v[i] = ok[i] ? *(const float4*)(pp[i] + cq * 4) : z4;
        *(float4*)op = make_float4(v[0].x, v[1].x, v[2].x, v[3].x); op += cstride;
        *(float4*)op = make_float4(v[0].y, v[1].y, v[2].y, v[3].y); op += cstride;
        *(float4*)op = make_float4(v[0].z, v[1].z, v[2].z, v[3].z); op += cstride;
        *(float4*)op = make_float4(v[0].w, v[1].w, v[2].w, v[3].w); op += cstride;
    }
}

// ---------------------------------------------------------------------------
// kernel_launch — graph-capturable, allocation-free
// ---------------------------------------------------------------------------
static inline int smem_for_nt(int nt) {
    return (2 * 64 * HS + 2 * 8 * nt * 8 * HS) * 2 + 4 * 64 * 4;
}

extern "C" void kernel_launch(void* const* d_in, const int* in_sizes, int n_in,
                              void* d_out, int out_size) {
    const float* pillars = (const float*)d_in[0];
    const int*   coors   = (const int*)d_in[1];
    const int*   npts    = (const int*)d_in[2];

    int wbase = (in_sizes[3] == 384) ? 3 : 4;  // skip batch_size slot if present
    const float* W1 = (const float*)d_in[wbase + 0];
    const float* g1 = (const float*)d_in[wbase + 1];
    const float* b1 = (const float*)d_in[wbase + 2];
    const float* m1 = (const float*)d_in[wbase + 3];
    const float* v1 = (const float*)d_in[wbase + 4];
    const float* W2 = (const float*)d_in[wbase + 5];
    const float* g2 = (const float*)d_in[wbase + 6];
    const float* b2 = (const float*)d_in[wbase + 7];
    const float* m2 = (const float*)d_in[wbase + 8];
    const float* v2 = (const float*)d_in[wbase + 9];

    int P = in_sizes[0] / (32 * 4);
    int B = out_size / (CO * XG * YG);
    if (B > BMAX) B = BMAX;
    if (P > PMAX) P = PMAX;
    int win = B * XG * YG;

    cudaFuncSetAttribute(mlp_nt_k<1>, cudaFuncAttributeMaxDynamicSharedMemorySize,
                         smem_for_nt(1));
    cudaFuncSetAttribute(mlp_nt_k<2>, cudaFuncAttributeMaxDynamicSharedMemorySize,
                         smem_for_nt(2));
    cudaFuncSetAttribute(mlp_nt_k<3>, cudaFuncAttributeMaxDynamicSharedMemorySize,
                         smem_for_nt(3));
    cudaFuncSetAttribute(mlp_nt_k<4>, cudaFuncAttributeMaxDynamicSharedMemorySize,
                         smem_for_nt(4));

    int nblk = (P + 7) / 8;

    init_winner_k<<<(win + 255) / 256, 256>>>(win);
    winner_k<<<(P + 255) / 256, 256>>>(coors, npts, P, B);
    mlp_nt_k<1><<<nblk, 256, smem_for_nt(1)>>>(pillars, coors, npts,
        W1, g1, b1, m1, v1, W2, g2, b2, m2, v2);
    mlp_nt_k<2><<<nblk, 256, smem_for_nt(2)>>>(pillars, coors, npts,
        W1, g1, b1, m1, v1, W2, g2, b2, m2, v2);
    mlp_nt_k<3><<<nblk, 256, smem_for_nt(3)>>>(pillars, coors, npts,
        W1, g1, b1, m1, v1, W2, g2, b2, m2, v2);
    mlp_nt_k<4><<<nblk, 256, smem_for_nt(4)>>>(pillars, coors, npts,
        W1, g1, b1, m1, v1, W2, g2, b2, m2, v2);
    emit_k<<<dim3(YG, 4 * B), 128>>>((float*)d_out);
}

// round 15
// speedup vs baseline: 1.2327x; 1.1107x over previous
#include <cuda_runtime.h>
#include <cuda_bf16.h>
#include <math.h>
#include <float.h>

#define XG 432
#define YG 496
#define CO 64
#define PMAX 64000
#define BMAX 4
#define HS 72   // bf16 stride per row (144 B): conflict-free fragment loads

// Scratch (no allocations allowed anywhere)
__device__ int   g_winner[BMAX * XG * YG];
__device__ float g_pooled[PMAX * CO];

// ---------------------------------------------------------------------------
// mma.sync m16n8k16 row.col f32 += bf16*bf16
// ---------------------------------------------------------------------------
__device__ __forceinline__ void mma_bf16(float d[4],
                                         unsigned a0, unsigned a1,
                                         unsigned a2, unsigned a3,
                                         unsigned b0, unsigned b1) {
    asm volatile(
        "mma.sync.aligned.m16n8k16.row.col.f32.bf16.bf16.f32 "
        "{%0,%1,%2,%3}, {%4,%5,%6,%7}, {%8,%9}, {%0,%1,%2,%3};"
        : "+f"(d[0]), "+f"(d[1]), "+f"(d[2]), "+f"(d[3])
        : "r"(a0), "r"(a1), "r"(a2), "r"(a3), "r"(b0), "r"(b1));
}

// ---------------------------------------------------------------------------
// Kernel 1: reset winner map
// ---------------------------------------------------------------------------
__global__ void init_winner_k(int n) {
    int i = blockIdx.x * blockDim.x + threadIdx.x;
    if (i < n) g_winner[i] = -1;
}

// ---------------------------------------------------------------------------
// Kernel 2: last-pillar-index-wins per BEV cell (deterministic via atomicMax)
// ---------------------------------------------------------------------------
__global__ void winner_k(const int* __restrict__ coors, int P, int B) {
    int p = blockIdx.x * blockDim.x + threadIdx.x;
    if (p >= P) return;
    int b = coors[4 * p + 0];
    int x = coors[4 * p + 1];
    int y = coors[4 * p + 2];
    if ((unsigned)b >= (unsigned)B || (unsigned)x >= XG || (unsigned)y >= YG)
        return;
    atomicMax(&g_winner[(b * XG + x) * YG + y], p);
}

// ---------------------------------------------------------------------------
// Kernel 3: PFN, split-bf16 3-pass tensor-core layer 2, WARP-PAIR per pillar.
// 256 threads = 8 warps = 4 pillars per block (pair p = warps 2p, 2p+1).
//   - each warp of a pair runs layer-1 for 16 of the pillar's 32 points
//   - each warp computes 2 m-tiles (32 of 64 output channels) of the GEMM
//   - pair-scoped named barrier between layer-1 and GEMM
// smem ~56KB -> 4 blocks/SM = 32 warps (2x occupancy vs round-10 winner).
// ---------------------------------------------------------------------------
__global__ __launch_bounds__(256, 4) void mlp_k(
    const float* __restrict__ pillars,
    const int*   __restrict__ coors,
    const int*   __restrict__ npoints,
    const float* __restrict__ W1, const float* __restrict__ g1,
    const float* __restrict__ b1, const float* __restrict__ m1,
    const float* __restrict__ v1,
    const float* __restrict__ W2, const float* __restrict__ g2,
    const float* __restrict__ b2, const float* __restrict__ m2,
    const float* __restrict__ v2, int P)
{
    extern __shared__ char smem[];
    __nv_bfloat16* s_w2hi = (__nv_bfloat16*)smem;          // [64][HS]
    __nv_bfloat16* s_w2lo = s_w2hi + 64 * HS;              // [64][HS]
    __nv_bfloat16* s_h1hi = s_w2lo + 64 * HS;              // [4][32][HS]
    __nv_bfloat16* s_h1lo = s_h1hi + 4 * 32 * HS;          // [4][32][HS]
    float* s_s2 = (float*)(s_h1lo + 4 * 32 * HS);          // [64]
    float* s_t2 = s_s2 + 64;                               // [64]

    const int tid  = threadIdx.x;
    const int w    = tid >> 5;
    const int lane = tid & 31;
    const int g    = lane >> 2;
    const int t4   = lane & 3;
    const int pair = w >> 1;      // 0..3 : pillar within block
    const int j    = w & 1;       // 0/1  : warp within pair

    // ---- stage W2 as bf16 hi/lo (once per block) ----
    for (int i = tid; i < 4096; i += 256) {
        int o = i >> 6, k = i & 63;
        float wv = W2[i];
        __nv_bfloat16 hi = __float2bfloat16_rn(wv);
        s_w2hi[o * HS + k] = hi;
        s_w2lo[o * HS + k] = __float2bfloat16_rn(wv - __bfloat162float(hi));
    }
    if (tid < 64) {
        float s2v = g2[tid] / sqrtf(v2[tid] + 1e-5f);
        s_s2[tid] = s2v;
        s_t2[tid] = b2[tid] - m2[tid] * s2v;
    }
    __syncthreads();   // orders W2/param staging for everyone

    const int pil = blockIdx.x * 4 + pair;
    const bool valid = (pil < P);

    __nv_bfloat16* h1hi = s_h1hi + pair * 32 * HS;
    __nv_bfloat16* h1lo = s_h1lo + pair * 32 * HS;

    if (valid) {
        // ---- features (lane = point; both warps of pair compute the same
        //      means redundantly -- L1-cached, keeps code straight-line) ----
        float4 pt = *(const float4*)&pillars[(pil * 32 + lane) * 4];
        float sx = pt.x, sy = pt.y, sz = pt.z;
        #pragma unroll
        for (int off = 16; off > 0; off >>= 1) {
            sx += __shfl_xor_sync(0xffffffffu, sx, off);
            sy += __shfl_xor_sync(0xffffffffu, sy, off);
            sz += __shfl_xor_sync(0xffffffffu, sz, off);
        }
        const int   npf = npoints[pil];
        const float fn  = (float)npf;
        const float cx = sx / fn, cy = sy / fn, cz = sz / fn;
        const float px = (float)coors[4 * pil + 1] * 0.16f + 0.08f;
        const float py = (float)coors[4 * pil + 2] * 0.16f - 39.6f;
        const float msk = (lane < npf) ? 1.0f : 0.0f;
        float f0 = pt.z * msk;
        float f1 = (pt.x - cx) * msk;
        float f2 = (pt.y - cy) * msk;
        float f3 = (pt.z - cz) * msk;
        float f4 = (pt.x - px) * msk;
        float f5 = (pt.y - py) * msk;

        // ---- layer-1 weights for this lane's 2 channels (folded BN1) ----
        const int c0 = 2 * lane, c1 = c0 + 1;
        float s1a = g1[c0] / sqrtf(v1[c0] + 1e-5f);
        float s1b = g1[c1] / sqrtf(v1[c1] + 1e-5f);
        float t1a = b1[c0] - m1[c0] * s1a;
        float t1b = b1[c1] - m1[c1] * s1b;
        float wa[6], wb[6];
        #pragma unroll
        for (int q = 0; q < 6; ++q) {
            wa[q] = W1[c0 * 6 + q] * s1a;
            wb[q] = W1[c1 * 6 + q] * s1b;
        }

        // ---- layer 1: THIS warp handles 16 of the 32 points ----
        const int pbase = j * 16;
        #pragma unroll 4
        for (int q = 0; q < 16; ++q) {
            int p = pbase + q;
            float e0 = __shfl_sync(0xffffffffu, f0, p);
            float e1 = __shfl_sync(0xffffffffu, f1, p);
            float e2 = __shfl_sync(0xffffffffu, f2, p);
            float e3 = __shfl_sync(0xffffffffu, f3, p);
            float e4 = __shfl_sync(0xffffffffu, f4, p);
            float e5 = __shfl_sync(0xffffffffu, f5, p);
            float ha = t1a, hb = t1b;
            ha = fmaf(e0, wa[0], ha);  hb = fmaf(e0, wb[0], hb);
            ha = fmaf(e1, wa[1], ha);  hb = fmaf(e1, wb[1], hb);
            ha = fmaf(e2, wa[2], ha);  hb = fmaf(e2, wb[2], hb);
            ha = fmaf(e3, wa[3], ha);  hb = fmaf(e3, wb[3], hb);
            ha = fmaf(e4, wa[4], ha);  hb = fmaf(e4, wb[4], hb);
            ha = fmaf(e5, wa[5], ha);  hb = fmaf(e5, wb[5], hb);
            ha = fmaxf(ha, 0.0f);
            hb = fmaxf(hb, 0.0f);
            __nv_bfloat162 hi2 = __floats2bfloat162_rn(ha, hb);
            float2 hf = __bfloat1622float2(hi2);
            __nv_bfloat162 lo2 = __floats2bfloat162_rn(ha - hf.x, hb - hf.y);
            *(__nv_bfloat162*)&h1hi[p * HS + c0] = hi2;   // bank = lane, CF
            *(__nv_bfloat162*)&h1lo[p * HS + c0] = lo2;
        }
    }

    // ---- pair-scoped barrier: both warps' h1 halves visible ----
    {
        unsigned bid = pair + 1;          // barriers 1..4
        asm volatile("bar.sync %0, %1;" :: "r"(bid), "r"(64) : "memory");
    }

    // ---- layer 2: this warp computes 2 m-tiles (o = 32j .. 32j+31),
    //      all 4 n-tiles (32 points), 3-pass split bf16 ----
    float d[2][4][4];
    #pragma unroll
    for (int m = 0; m < 2; ++m)
        #pragma unroll
        for (int n = 0; n < 4; ++n)
            #pragma unroll
            for (int r = 0; r < 4; ++r) d[m][n][r] = 0.0f;

    const int mbase = 2 * j;   // m tiles {2j, 2j+1}

    #pragma unroll
    for (int kt = 0; kt < 4; ++kt) {
        const int kA = kt * 16 + 2 * t4;
        const int kB = kA + 8;

        unsigned ahi[2][4];
        #pragma unroll
        for (int m = 0; m < 2; ++m) {
            int r0 = (16 * (mbase + m) + g) * HS, r1 = r0 + 8 * HS;
            ahi[m][0] = *(const unsigned*)&s_w2hi[r0 + kA];
            ahi[m][1] = *(const unsigned*)&s_w2hi[r1 + kA];
            ahi[m][2] = *(const unsigned*)&s_w2hi[r0 + kB];
            ahi[m][3] = *(const unsigned*)&s_w2hi[r1 + kB];
        }
        unsigned bhi[4][2], blo[4][2];
        #pragma unroll
        for (int n = 0; n < 4; ++n) {
            int pr = (8 * n + g) * HS;
            bhi[n][0] = *(const unsigned*)&h1hi[pr + kA];
            bhi[n][1] = *(const unsigned*)&h1hi[pr + kB];
            blo[n][0] = *(const unsigned*)&h1lo[pr + kA];
            blo[n][1] = *(const unsigned*)&h1lo[pr + kB];
        }
        #pragma unroll
        for (int m = 0; m < 2; ++m)
            #pragma unroll
            for (int n = 0; n < 4; ++n) {
                mma_bf16(d[m][n], ahi[m][0], ahi[m][1], ahi[m][2], ahi[m][3],
                         bhi[n][0], bhi[n][1]);
                mma_bf16(d[m][n], ahi[m][0], ahi[m][1], ahi[m][2], ahi[m][3],
                         blo[n][0], blo[n][1]);
            }
        unsigned alo[2][4];
        #pragma unroll
        for (int m = 0; m < 2; ++m) {
            int r0 = (16 * (mbase + m) + g) * HS, r1 = r0 + 8 * HS;
            alo[m][0] = *(const unsigned*)&s_w2lo[r0 + kA];
            alo[m][1] = *(const unsigned*)&s_w2lo[r1 + kA];
            alo[m][2] = *(const unsigned*)&s_w2lo[r0 + kB];
            alo[m][3] = *(const unsigned*)&s_w2lo[r1 + kB];
        }
        #pragma unroll
        for (int m = 0; m < 2; ++m)
            #pragma unroll
            for (int n = 0; n < 4; ++n)
                mma_bf16(d[m][n], alo[m][0], alo[m][1], alo[m][2], alo[m][3],
                         bhi[n][0], bhi[n][1]);
    }

    // ---- epilogue: BN2 (sign-safe), max over all 32 points ----
    #pragma unroll
    for (int m = 0; m < 2; ++m) {
        float mxA = -FLT_MAX, mnA = FLT_MAX;   // row o = 16(mbase+m) + g
        float mxB = -FLT_MAX, mnB = FLT_MAX;   // row o = ... + 8
        #pragma unroll
        for (int n = 0; n < 4; ++n) {
            mxA = fmaxf(mxA, fmaxf(d[m][n][0], d[m][n][1]));
            mnA = fminf(mnA, fminf(d[m][n][0], d[m][n][1]));
            mxB = fmaxf(mxB, fmaxf(d[m][n][2], d[m][n][3]));
            mnB = fminf(mnB, fminf(d[m][n][2], d[m][n][3]));
        }
        #pragma unroll
        for (int off = 1; off <= 2; off <<= 1) {
            mxA = fmaxf(mxA, __shfl_xor_sync(0xffffffffu, mxA, off));
            mnA = fminf(mnA, __shfl_xor_sync(0xffffffffu, mnA, off));
            mxB = fmaxf(mxB, __shfl_xor_sync(0xffffffffu, mxB, off));
            mnB = fminf(mnB, __shfl_xor_sync(0xffffffffu, mnB, off));
        }
        if (t4 == 0 && valid) {
            int oA = 16 * (mbase + m) + g, oB = oA + 8;
            float sA = s_s2[oA], sB = s_s2[oB];
            float vA = (sA >= 0.0f) ? fmaf(sA, mxA, s_t2[oA])
                                    : fmaf(sA, mnA, s_t2[oA]);
            float vB = (sB >= 0.0f) ? fmaf(sB, mxB, s_t2[oB])
                                    : fmaf(sB, mnB, s_t2[oB]);
            g_pooled[pil * 64 + oA] = vA;
            g_pooled[pil * 64 + oB] = vB;
        }
    }
}

// ---------------------------------------------------------------------------
// Kernel 4: emit pseudo-image (B, C, Y, X). grid = (YG, 4*B), 128 threads.
// ---------------------------------------------------------------------------
__global__ __launch_bounds__(128) void emit_k(float* __restrict__ out) {
    __shared__ int s_wi[XG];
    const int y    = blockIdx.x;
    const int b    = blockIdx.y >> 2;
    const int part = blockIdx.y & 3;
    for (int x = threadIdx.x; x < XG; x += 128)
        s_wi[x] = g_winner[(b * XG + x) * YG + y];
    __syncthreads();

    const int t = threadIdx.x;
    if (t >= XG / 4) return;   // 108 active threads
    const int x0 = t * 4;

    const float* pp[4];
    bool ok[4];
    #pragma unroll
    for (int i = 0; i < 4; ++i) {
        int wi = s_wi[x0 + i];
        ok[i] = (wi >= 0);
        pp[i] = g_pooled + (ok[i] ? wi : 0) * 64;
    }

    const float4 z4 = make_float4(0.f, 0.f, 0.f, 0.f);
    const long long cstride = (long long)YG * XG;
    float* op = out + ((long long)b * CO + part * 16) * cstride
                    + (long long)y * XG + x0;

    #pragma unroll
    for (int cq = part * 4; cq < part * 4 + 4; ++cq) {
        float4 v[4];
        #pragma unroll
        for (int i = 0; i < 4; ++i)
            v[i] = ok[i] ? *(const float4*)(pp[i] + cq * 4) : z4;
        *(float4*)op = make_float4(v[0].x, v[1].x, v[2].x, v[3].x); op += cstride;
        *(float4*)op = make_float4(v[0].y, v[1].y, v[2].y, v[3].y); op += cstride;
        *(float4*)op = make_float4(v[0].z, v[1].z, v[2].z, v[3].z); op += cstride;
        *(float4*)op = make_float4(v[0].w, v[1].w, v[2].w, v[3].w); op += cstride;
    }
}

// ---------------------------------------------------------------------------
// kernel_launch — graph-capturable, allocation-free
// ---------------------------------------------------------------------------
extern "C" void kernel_launch(void* const* d_in, const int* in_sizes, int n_in,
                              void* d_out, int out_size) {
    const float* pillars = (const float*)d_in[0];
    const int*   coors   = (const int*)d_in[1];
    const int*   npts    = (const int*)d_in[2];

    int wbase = (in_sizes[3] == 384) ? 3 : 4;  // skip batch_size slot if present
    const float* W1 = (const float*)d_in[wbase + 0];
    const float* g1 = (const float*)d_in[wbase + 1];
    const float* b1 = (const float*)d_in[wbase + 2];
    const float* m1 = (const float*)d_in[wbase + 3];
    const float* v1 = (const float*)d_in[wbase + 4];
    const float* W2 = (const float*)d_in[wbase + 5];
    const float* g2 = (const float*)d_in[wbase + 6];
    const float* b2 = (const float*)d_in[wbase + 7];
    const float* m2 = (const float*)d_in[wbase + 8];
    const float* v2 = (const float*)d_in[wbase + 9];

    int P = in_sizes[0] / (32 * 4);
    int B = out_size / (CO * XG * YG);
    if (B > BMAX) B = BMAX;
    if (P > PMAX) P = PMAX;
    int win = B * XG * YG;

    // smem: W2 hi/lo (2*64*HS) + h1 hi/lo (2*4*32*HS) bf16 + s2/t2 fp32
    const int smemBytes = (2 * 64 * HS + 2 * 4 * 32 * HS) * 2 + 2 * 64 * 4;
    cudaFuncSetAttribute(mlp_k, cudaFuncAttributeMaxDynamicSharedMemorySize,
                         smemBytes);

    init_winner_k<<<(win + 255) / 256, 256>>>(win);
    winner_k<<<(P + 255) / 256, 256>>>(coors, P, B);
    mlp_k<<<(P + 3) / 4, 256, smemBytes>>>(pillars, coors, npts,
                                           W1, g1, b1, m1, v1,
                                           W2, g2, b2, m2, v2, P);
    emit_k<<<dim3(YG, 4 * B), 128>>>((float*)d_out);
}

// round 16
// speedup vs baseline: 1.6083x; 1.3046x over previous
#include <cuda_runtime.h>
#include <cuda_bf16.h>
#include <math.h>
#include <float.h>

#define XG 432
#define YG 496
#define CO 64
#define PMAX 64000
#define BMAX 4
#define HS 72   // bf16 stride per row (144 B): conflict-free fragment loads

// Scratch (no allocations allowed anywhere)
__device__ int   g_winner[BMAX * XG * YG];
__device__ float g_pooled[PMAX * CO];

// ---------------------------------------------------------------------------
// mma.sync m16n8k16 row.col f32 += bf16*bf16
// ---------------------------------------------------------------------------
__device__ __forceinline__ void mma_bf16(float d[4],
                                         unsigned a0, unsigned a1,
                                         unsigned a2, unsigned a3,
                                         unsigned b0, unsigned b1) {
    asm volatile(
        "mma.sync.aligned.m16n8k16.row.col.f32.bf16.bf16.f32 "
        "{%0,%1,%2,%3}, {%4,%5,%6,%7}, {%8,%9}, {%0,%1,%2,%3};"
        : "+f"(d[0]), "+f"(d[1]), "+f"(d[2]), "+f"(d[3])
        : "r"(a0), "r"(a1), "r"(a2), "r"(a3), "r"(b0), "r"(b1));
}

// ---------------------------------------------------------------------------
// Kernel 1: reset winner map
// ---------------------------------------------------------------------------
__global__ void init_winner_k(int n) {
    int i = blockIdx.x * blockDim.x + threadIdx.x;
    if (i < n) g_winner[i] = -1;
}

// ---------------------------------------------------------------------------
// Kernel 2: PFN with split-bf16 tensor-core layer 2 (R10 structure) with
// latency hoisting: ALL per-warp global loads (pillar points, coors, npf,
// W1/BN1 params) issue at kernel entry so their DRAM latency overlaps the
// W2 staging phase + barrier. Winner atomicMax folded in (coors in regs).
// 256 threads = 8 warps = 8 pillars per block; warp owns a pillar end-to-end.
// ---------------------------------------------------------------------------
__global__ __launch_bounds__(256) void mlp_k(
    const float* __restrict__ pillars,
    const int*   __restrict__ coors,
    const int*   __restrict__ npoints,
    const float* __restrict__ W1, const float* __restrict__ g1,
    const float* __restrict__ b1, const float* __restrict__ m1,
    const float* __restrict__ v1,
    const float* __restrict__ W2, const float* __restrict__ g2,
    const float* __restrict__ b2, const float* __restrict__ m2,
    const float* __restrict__ v2, int P, int B)
{
    extern __shared__ char smem[];
    __nv_bfloat16* s_w2hi = (__nv_bfloat16*)smem;          // [64][HS]
    __nv_bfloat16* s_w2lo = s_w2hi + 64 * HS;              // [64][HS]
    __nv_bfloat16* s_h1hi = s_w2lo + 64 * HS;              // [8][32][HS]
    __nv_bfloat16* s_h1lo = s_h1hi + 8 * 32 * HS;          // [8][32][HS]
    float* s_s2 = (float*)(s_h1lo + 8 * 32 * HS);          // [64]
    float* s_t2 = s_s2 + 64;                               // [64]

    const int tid  = threadIdx.x;
    const int w    = tid >> 5;
    const int lane = tid & 31;
    const int g    = lane >> 2;
    const int t4   = lane & 3;

    const int pil = blockIdx.x * 8 + w;
    const bool valid = (pil < P);

    // ============== ENTRY: issue ALL long-latency loads NOW ==============
    // (their completion overlaps W2 staging below)
    float4 pt = make_float4(0.f, 0.f, 0.f, 0.f);
    int cb = 0, cxi = 0, cyi = 0, npf = 1;
    if (valid) {
        pt  = *(const float4*)&pillars[(pil * 32 + lane) * 4];
        cb  = __ldg(&coors[4 * pil + 0]);
        cxi = __ldg(&coors[4 * pil + 1]);
        cyi = __ldg(&coors[4 * pil + 2]);
        npf = __ldg(&npoints[pil]);
    }
    // W1 / BN1 params for this lane's 2 channels (pillar-independent)
    const int c0 = 2 * lane, c1 = c0 + 1;
    const float s1a = g1[c0] / sqrtf(v1[c0] + 1e-5f);
    const float s1b = g1[c1] / sqrtf(v1[c1] + 1e-5f);
    const float t1a = b1[c0] - m1[c0] * s1a;
    const float t1b = b1[c1] - m1[c1] * s1b;
    float wa[6], wb[6];
    #pragma unroll
    for (int q = 0; q < 6; ++q) {
        wa[q] = W1[c0 * 6 + q] * s1a;
        wb[q] = W1[c1 * 6 + q] * s1b;
    }

    // ---- winner scatter (last-pillar-wins via atomicMax), coors in regs ----
    if (valid && lane == 0) {
        if ((unsigned)cb < (unsigned)B && (unsigned)cxi < XG &&
            (unsigned)cyi < YG)
            atomicMax(&g_winner[(cb * XG + cxi) * YG + cyi], pil);
    }

    // ---- stage W2 as bf16 hi/lo, vectorized LDG.128 (4 per thread) ----
    #pragma unroll
    for (int i = tid; i < 1024; i += 256) {
        int o = i >> 4, k4 = (i & 15) * 4;
        float4 wv = *(const float4*)&W2[o * 64 + k4];
        __nv_bfloat16* hid = &s_w2hi[o * HS + k4];
        __nv_bfloat16* lod = &s_w2lo[o * HS + k4];
        __nv_bfloat162 h01 = __floats2bfloat162_rn(wv.x, wv.y);
        __nv_bfloat162 h23 = __floats2bfloat162_rn(wv.z, wv.w);
        float2 f01 = __bfloat1622float2(h01);
        float2 f23 = __bfloat1622float2(h23);
        *(__nv_bfloat162*)(hid)     = h01;
        *(__nv_bfloat162*)(hid + 2) = h23;
        *(__nv_bfloat162*)(lod)     = __floats2bfloat162_rn(wv.x - f01.x,
                                                            wv.y - f01.y);
        *(__nv_bfloat162*)(lod + 2) = __floats2bfloat162_rn(wv.z - f23.x,
                                                            wv.w - f23.y);
    }
    if (tid < 64) {
        float s2v = g2[tid] / sqrtf(v2[tid] + 1e-5f);
        s_s2[tid] = s2v;
        s_t2[tid] = b2[tid] - m2[tid] * s2v;
    }
    __syncthreads();   // last block-wide sync

    __nv_bfloat16* h1hi = s_h1hi + w * 32 * HS;
    __nv_bfloat16* h1lo = s_h1lo + w * 32 * HS;

    if (valid) {
        // ---- features (lane = point); pillar data already in registers ----
        float sx = pt.x, sy = pt.y, sz = pt.z;
        #pragma unroll
        for (int off = 16; off > 0; off >>= 1) {
            sx += __shfl_xor_sync(0xffffffffu, sx, off);
            sy += __shfl_xor_sync(0xffffffffu, sy, off);
            sz += __shfl_xor_sync(0xffffffffu, sz, off);
        }
        const float fn  = (float)npf;
        const float cx = sx / fn, cy = sy / fn, cz = sz / fn;
        const float px = (float)cxi * 0.16f + 0.08f;
        const float py = (float)cyi * 0.16f - 39.6f;
        const float msk = (lane < npf) ? 1.0f : 0.0f;
        float f0 = pt.z * msk;
        float f1 = (pt.x - cx) * msk;
        float f2 = (pt.y - cy) * msk;
        float f3 = (pt.z - cz) * msk;
        float f4 = (pt.x - px) * msk;
        float f5 = (pt.y - py) * msk;

        // ---- layer 1: per point p, this lane computes channels c0,c1 ----
        #pragma unroll 4
        for (int p = 0; p < 32; ++p) {
            float e0 = __shfl_sync(0xffffffffu, f0, p);
            float e1 = __shfl_sync(0xffffffffu, f1, p);
            float e2 = __shfl_sync(0xffffffffu, f2, p);
            float e3 = __shfl_sync(0xffffffffu, f3, p);
            float e4 = __shfl_sync(0xffffffffu, f4, p);
            float e5 = __shfl_sync(0xffffffffu, f5, p);
            float ha = t1a, hb = t1b;
            ha = fmaf(e0, wa[0], ha);  hb = fmaf(e0, wb[0], hb);
            ha = fmaf(e1, wa[1], ha);  hb = fmaf(e1, wb[1], hb);
            ha = fmaf(e2, wa[2], ha);  hb = fmaf(e2, wb[2], hb);
            ha = fmaf(e3, wa[3], ha);  hb = fmaf(e3, wb[3], hb);
            ha = fmaf(e4, wa[4], ha);  hb = fmaf(e4, wb[4], hb);
            ha = fmaf(e5, wa[5], ha);  hb = fmaf(e5, wb[5], hb);
            ha = fmaxf(ha, 0.0f);
            hb = fmaxf(hb, 0.0f);
            __nv_bfloat162 hi2 = __floats2bfloat162_rn(ha, hb);
            float2 hf = __bfloat1622float2(hi2);
            __nv_bfloat162 lo2 = __floats2bfloat162_rn(ha - hf.x, hb - hf.y);
            *(__nv_bfloat162*)&h1hi[p * HS + c0] = hi2;   // bank = lane, CF
            *(__nv_bfloat162*)&h1lo[p * HS + c0] = lo2;
        }
    }
    __syncwarp();

    // ---- layer 2: D[64 o][32 pt] via 4 mtiles x 4 ntiles x 4 ktiles ----
    float d[4][4][4];
    #pragma unroll
    for (int m = 0; m < 4; ++m)
        #pragma unroll
        for (int n = 0; n < 4; ++n)
            #pragma unroll
            for (int r = 0; r < 4; ++r) d[m][n][r] = 0.0f;

    #pragma unroll
    for (int kt = 0; kt < 4; ++kt) {
        const int kA = kt * 16 + 2 * t4;
        const int kB = kA + 8;

        unsigned ahi[4][4];
        #pragma unroll
        for (int m = 0; m < 4; ++m) {
            int r0 = (16 * m + g) * HS, r1 = r0 + 8 * HS;
            ahi[m][0] = *(const unsigned*)&s_w2hi[r0 + kA];
            ahi[m][1] = *(const unsigned*)&s_w2hi[r1 + kA];
            ahi[m][2] = *(const unsigned*)&s_w2hi[r0 + kB];
            ahi[m][3] = *(const unsigned*)&s_w2hi[r1 + kB];
        }
        unsigned bhi[4][2], blo[4][2];
        #pragma unroll
        for (int n = 0; n < 4; ++n) {
            int pr = (8 * n + g) * HS;
            bhi[n][0] = *(const unsigned*)&h1hi[pr + kA];
            bhi[n][1] = *(const unsigned*)&h1hi[pr + kB];
            blo[n][0] = *(const unsigned*)&h1lo[pr + kA];
            blo[n][1] = *(const unsigned*)&h1lo[pr + kB];
        }
        // hi*hi and hi*lo passes
        #pragma unroll
        for (int m = 0; m < 4; ++m)
            #pragma unroll
            for (int n = 0; n < 4; ++n) {
                mma_bf16(d[m][n], ahi[m][0], ahi[m][1], ahi[m][2], ahi[m][3],
                         bhi[n][0], bhi[n][1]);
                mma_bf16(d[m][n], ahi[m][0], ahi[m][1], ahi[m][2], ahi[m][3],
                         blo[n][0], blo[n][1]);
            }
        // lo*hi pass
        unsigned alo[4][4];
        #pragma unroll
        for (int m = 0; m < 4; ++m) {
            int r0 = (16 * m + g) * HS, r1 = r0 + 8 * HS;
            alo[m][0] = *(const unsigned*)&s_w2lo[r0 + kA];
            alo[m][1] = *(const unsigned*)&s_w2lo[r1 + kA];
            alo[m][2] = *(const unsigned*)&s_w2lo[r0 + kB];
            alo[m][3] = *(const unsigned*)&s_w2lo[r1 + kB];
        }
        #pragma unroll
        for (int m = 0; m < 4; ++m)
            #pragma unroll
            for (int n = 0; n < 4; ++n)
                mma_bf16(d[m][n], alo[m][0], alo[m][1], alo[m][2], alo[m][3],
                         bhi[n][0], bhi[n][1]);
    }

    // ---- epilogue: BN2 (sign-safe via max&min), max over points ----
    #pragma unroll
    for (int m = 0; m < 4; ++m) {
        float mxA = -FLT_MAX, mnA = FLT_MAX;   // row o = 16m + g
        float mxB = -FLT_MAX, mnB = FLT_MAX;   // row o = 16m + g + 8
        #pragma unroll
        for (int n = 0; n < 4; ++n) {
            mxA = fmaxf(mxA, fmaxf(d[m][n][0], d[m][n][1]));
            mnA = fminf(mnA, fminf(d[m][n][0], d[m][n][1]));
            mxB = fmaxf(mxB, fmaxf(d[m][n][2], d[m][n][3]));
            mnB = fminf(mnB, fminf(d[m][n][2], d[m][n][3]));
        }
        #pragma unroll
        for (int off = 1; off <= 2; off <<= 1) {
            mxA = fmaxf(mxA, __shfl_xor_sync(0xffffffffu, mxA, off));
            mnA = fminf(mnA, __shfl_xor_sync(0xffffffffu, mnA, off));
            mxB = fmaxf(mxB, __shfl_xor_sync(0xffffffffu, mxB, off));
            mnB = fminf(mnB, __shfl_xor_sync(0xffffffffu, mnB, off));
        }
        if (t4 == 0 && valid) {
            int oA = 16 * m + g, oB = oA + 8;
            float sA = s_s2[oA], sB = s_s2[oB];
            float vA = (sA >= 0.0f) ? fmaf(sA, mxA, s_t2[oA])
                                    : fmaf(sA, mnA, s_t2[oA]);
            float vB = (sB >= 0.0f) ? fmaf(sB, mxB, s_t2[oB])
                                    : fmaf(sB, mnB, s_t2[oB]);
            g_pooled[pil * 64 + oA] = vA;
            g_pooled[pil * 64 + oB] = vB;
        }
    }
}

// ---------------------------------------------------------------------------
// Kernel 3: emit pseudo-image (B, C, Y, X). grid = (YG, 4*B), 128 threads.
// ---------------------------------------------------------------------------
__global__ __launch_bounds__(128) void emit_k(float* __restrict__ out) {
    __shared__ int s_wi[XG];
    const int y    = blockIdx.x;
    const int b    = blockIdx.y >> 2;
    const int part = blockIdx.y & 3;
    for (int x = threadIdx.x; x < XG; x += 128)
        s_wi[x] = g_winner[(b * XG + x) * YG + y];
    __syncthreads();

    const int t = threadIdx.x;
    if (t >= XG / 4) return;   // 108 active threads
    const int x0 = t * 4;

    const float* pp[4];
    bool ok[4];
    #pragma unroll
    for (int i = 0; i < 4; ++i) {
        int wi = s_wi[x0 + i];
        ok[i] = (wi >= 0);
        pp[i] = g_pooled + (ok[i] ? wi : 0) * 64;
    }

    const float4 z4 = make_float4(0.f, 0.f, 0.f, 0.f);
    const long long cstride = (long long)YG * XG;
    float* op = out + ((long long)b * CO + part * 16) * cstride
                    + (long long)y * XG + x0;

    #pragma unroll
    for (int cq = part * 4; cq < part * 4 + 4; ++cq) {
        float4 v[4];
        #pragma unroll
        for (int i = 0; i < 4; ++i)
            v[i] = ok[i] ? *(const float4*)(pp[i] + cq * 4) : z4;
        *(float4*)op = make_float4(v[0].x, v[1].x, v[2].x, v[3].x); op += cstride;
        *(float4*)op = make_float4(v[0].y, v[1].y, v[2].y, v[3].y); op += cstride;
        *(float4*)op = make_float4(v[0].z, v[1].z, v[2].z, v[3].z); op += cstride;
        *(float4*)op = make_float4(v[0].w, v[1].w, v[2].w, v[3].w); op += cstride;
    }
}

// ---------------------------------------------------------------------------
// kernel_launch — graph-capturable, allocation-free
// ---------------------------------------------------------------------------
extern "C" void kernel_launch(void* const* d_in, const int* in_sizes, int n_in,
                              void* d_out, int out_size) {
    const float* pillars = (const float*)d_in[0];
    const int*   coors   = (const int*)d_in[1];
    const int*   npts    = (const int*)d_in[2];

    int wbase = (in_sizes[3] == 384) ? 3 : 4;  // skip batch_size slot if present
    const float* W1 = (const float*)d_in[wbase + 0];
    const float* g1 = (const float*)d_in[wbase + 1];
    const float* b1 = (const float*)d_in[wbase + 2];
    const float* m1 = (const float*)d_in[wbase + 3];
    const float* v1 = (const float*)d_in[wbase + 4];
    const float* W2 = (const float*)d_in[wbase + 5];
    const float* g2 = (const float*)d_in[wbase + 6];
    const float* b2 = (const float*)d_in[wbase + 7];
    const float* m2 = (const float*)d_in[wbase + 8];
    const float* v2 = (const float*)d_in[wbase + 9];

    int P = in_sizes[0] / (32 * 4);
    int B = out_size / (CO * XG * YG);
    if (B > BMAX) B = BMAX;
    if (P > PMAX) P = PMAX;
    int win = B * XG * YG;

    // smem: W2 hi/lo (2*64*HS) + h1 hi/lo (2*8*32*HS) bf16 + s2/t2 fp32
    const int smemBytes = (2 * 64 * HS + 2 * 8 * 32 * HS) * 2 + 2 * 64 * 4;
    cudaFuncSetAttribute(mlp_k, cudaFuncAttributeMaxDynamicSharedMemorySize,
                         smemBytes);

    init_winner_k<<<(win + 255) / 256, 256>>>(win);
    mlp_k<<<(P + 7) / 8, 256, smemBytes>>>(pillars, coors, npts,
                                           W1, g1, b1, m1, v1,
                                           W2, g2, b2, m2, v2, P, B);
    emit_k<<<dim3(YG, 4 * B), 128>>>((float*)d_out);
}